// round 9
// baseline (speedup 1.0000x reference)
#include <cuda_runtime.h>
#include <cuda_fp16.h>
#include <math.h>
#include <stdint.h>

// ---------------------------------------------------------------------------
// Problem constants
// ---------------------------------------------------------------------------
#define BATCH 4
#define SEQ   4096
#define DIM   1024
#define MTOT  (BATCH * SEQ)     // 16384

#define NTHR_G 512              // 16 warps per GEMM CTA (2x8 grid of 64x32 tiles)
#define STAGES 3
#define BK     64               // halves per k-chunk (128 B per row)
#define BM     128
#define BN     256
#define A_TILE_B 16384          // 128 rows x 128 bytes
#define B_TILE_B 32768          // 256 rows x 128 bytes
#define STAGE_B (A_TILE_B + B_TILE_B)      // 49152
#define SMEM_BYTES (STAGES * STAGE_B)      // 147456 (1 CTA/SM)

// ---------------------------------------------------------------------------
// Scratch (__device__ globals: allocation-free rule)
// ---------------------------------------------------------------------------
__device__ __half g_xh[MTOT * DIM];                  // fp16 x
__device__ __half g_wth[3 * DIM * DIM];              // W^T fp16 (q,k,v)
__device__ __half g_qh[MTOT * DIM];
__device__ __half g_kh[MTOT * DIM];
__device__ __half g_vh[MTOT * DIM];
__device__ __half g_vth[(size_t)BATCH * DIM * SEQ];  // v^T fp16
__device__ __half g_sh[(size_t)BATCH * SEQ * SEQ];   // UNNORMALIZED exp weights fp16
__device__ float  g_l[MTOT];                         // per-row weight sums

// ---------------------------------------------------------------------------
// Helpers
// ---------------------------------------------------------------------------
__device__ __forceinline__ uint32_t smem_u32(const void* p) {
    return (uint32_t)__cvta_generic_to_shared(p);
}

__device__ __forceinline__ void cp16(uint32_t dst, const void* src) {
    asm volatile("cp.async.cg.shared.global [%0], [%1], 16;\n" :: "r"(dst), "l"(src));
}
#define CP_COMMIT() asm volatile("cp.async.commit_group;\n")
#define CP_WAIT1()  asm volatile("cp.async.wait_group 1;\n")
#define CP_WAIT0()  asm volatile("cp.async.wait_group 0;\n")

__device__ __forceinline__ void ldsm4(uint32_t* r, uint32_t addr) {
    asm volatile("ldmatrix.sync.aligned.m8n8.x4.shared.b16 {%0,%1,%2,%3}, [%4];"
                 : "=r"(r[0]), "=r"(r[1]), "=r"(r[2]), "=r"(r[3]) : "r"(addr));
}

__device__ __forceinline__ void mma16(float* d, const uint32_t* a, const uint32_t* b) {
    asm volatile(
        "mma.sync.aligned.m16n8k16.row.col.f32.f16.f16.f32 "
        "{%0,%1,%2,%3}, {%4,%5,%6,%7}, {%8,%9}, {%0,%1,%2,%3};\n"
        : "+f"(d[0]), "+f"(d[1]), "+f"(d[2]), "+f"(d[3])
        : "r"(a[0]), "r"(a[1]), "r"(a[2]), "r"(a[3]), "r"(b[0]), "r"(b[1]));
}

// exp2 with clamp: keeps fp16 finite even for pathological scores
__device__ __forceinline__ float wexp(float s, float c2) {
    return exp2f(fminf(s * c2, 15.0f));
}

// ---------------------------------------------------------------------------
// Tile fills: rows x 64 halves (128B/row), swizzled chunk = c16 ^ (r&7).
// 512 threads. A tile: 128 rows (2 chunks/thread). B tile: 256 rows (4).
// ---------------------------------------------------------------------------
__device__ __forceinline__ void fill_a(uint32_t sdst, const __half* __restrict__ g,
                                       int ld, int k0) {
    const int tid = threadIdx.x;
#pragma unroll
    for (int i = 0; i < 2; i++) {
        int c = tid + i * 512;
        int r = c >> 3, c16 = c & 7;
        cp16(sdst + r * 128 + ((c16 ^ (r & 7)) << 4),
             g + (size_t)r * ld + k0 + c16 * 8);
    }
}

__device__ __forceinline__ void fill_b(uint32_t sdst, const __half* __restrict__ g,
                                       int ld, int k0) {
    const int tid = threadIdx.x;
#pragma unroll
    for (int i = 0; i < 4; i++) {
        int c = tid + i * 512;
        int r = c >> 3, c16 = c & 7;
        cp16(sdst + r * 128 + ((c16 ^ (r & 7)) << 4),
             g + (size_t)r * ld + k0 + c16 * 8);
    }
}

// ---------------------------------------------------------------------------
// Unified NT fp16 GEMM: C[128x256 tile] = A(row-major,K-contig) . B^T
// 16 warps (2x8 grid), warp tile 64x32, m16n8k16, 3-stage cp.async pipeline,
// one barrier per K-iter.
// MODE 0: QKV    A=g_xh,  B=g_wth[z], C=g_qh/g_kh/g_vh (+bias fp32, ->fp16)
// MODE 1: scores A=g_qh[z],B=g_kh[z], C=g_sh: w = exp2(s*c2) fp16, causal mask
// MODE 2: PV     A=g_sh[z],B=g_vth[z],C=out fp32 scaled by 1/g_l[row]
// ---------------------------------------------------------------------------
template <int MODE>
__global__ __launch_bounds__(NTHR_G, 1)
void gemm_nt(float* __restrict__ Cout,
             const float* __restrict__ b0, const float* __restrict__ b1,
             const float* __restrict__ b2)
{
    const int row0 = blockIdx.y * BM;
    const int col0 = blockIdx.x * BN;
    const int z = blockIdx.z;
    if (MODE == 1 && col0 > row0) return;   // fully above the diagonal

    const __half *A, *B;
    const float* bias = nullptr;
    __half* Ch = nullptr;
    float* Cf = nullptr;
    int lda, ldb, ldc, nK;
    if (MODE == 0) {
        A = g_xh; lda = DIM;
        B = g_wth + (size_t)z * DIM * DIM; ldb = DIM;
        Ch = (z == 0 ? g_qh : (z == 1 ? g_kh : g_vh)); ldc = DIM;
        bias = (z == 0 ? b0 : (z == 1 ? b1 : b2));
        nK = DIM / BK;
    } else if (MODE == 1) {
        A = g_qh + (size_t)z * SEQ * DIM; lda = DIM;
        B = g_kh + (size_t)z * SEQ * DIM; ldb = DIM;
        Ch = g_sh + (size_t)z * SEQ * SEQ; ldc = SEQ;
        nK = DIM / BK;
    } else {
        A = g_sh + (size_t)z * SEQ * SEQ; lda = SEQ;
        B = g_vth + (size_t)z * DIM * SEQ; ldb = SEQ;
        Cf = Cout + (size_t)z * SEQ * DIM; ldc = DIM;
        nK = (row0 + BM) / BK;
    }
    const __half* Arow = A + (size_t)row0 * lda;
    const __half* Brow = B + (size_t)col0 * ldb;

    extern __shared__ char smem[];
    const uint32_t sbase = smem_u32(smem);

    const int tid  = threadIdx.x;
    const int lane = tid & 31, warp = tid >> 5;
    const int wm = warp & 1, wn = warp >> 1;      // 2x8 warp grid: 64x32 tiles
    const int mat = lane >> 3, rl = lane & 7;     // ldmatrix address lanes

    float acc[4][4][4];
#pragma unroll
    for (int i = 0; i < 4; i++)
#pragma unroll
        for (int j = 0; j < 4; j++)
#pragma unroll
            for (int t = 0; t < 4; t++) acc[i][j][t] = 0.0f;

    // prologue: stages 0 and 1
    fill_a(sbase, Arow, lda, 0);
    fill_b(sbase + A_TILE_B, Brow, ldb, 0);
    CP_COMMIT();
    fill_a(sbase + STAGE_B, Arow, lda, BK);
    fill_b(sbase + STAGE_B + A_TILE_B, Brow, ldb, BK);
    CP_COMMIT();

    for (int it = 0; it < nK; ++it) {
        if (it + 1 < nK) { CP_WAIT1(); } else { CP_WAIT0(); }
        __syncthreads();
        // Barrier proves all warps finished reading stage (it-1), so the
        // prefetch into slot (it+2)%3 == (it-1)%3 is safe: one barrier/iter.
        if (it + 2 < nK) {
            const int slot = (it + 2) % STAGES;
            fill_a(sbase + slot * STAGE_B, Arow, lda, (it + 2) * BK);
            fill_b(sbase + slot * STAGE_B + A_TILE_B, Brow, ldb, (it + 2) * BK);
            CP_COMMIT();
        }

        const uint32_t sA = sbase + (it % STAGES) * STAGE_B;
        const uint32_t sB = sA + A_TILE_B;

#pragma unroll
        for (int kk = 0; kk < 4; kk++) {          // 4 x k16 per BK=64
            const int klo = kk * 2;               // 16B chunk index

            uint32_t a[4][4];
#pragma unroll
            for (int mt = 0; mt < 4; mt++) {
                int row = wm * 64 + mt * 16 + ((mat & 1) << 3) + rl;
                int c16 = klo + (mat >> 1);
                ldsm4(a[mt], sA + row * 128 + ((c16 ^ (row & 7)) << 4));
            }
            uint32_t b[4][2];
#pragma unroll
            for (int t = 0; t < 2; t++) {
                int nrow = wn * 32 + t * 16 + ((mat >> 1) << 3) + rl;
                int c16 = klo + (mat & 1);
                uint32_t r4[4];
                ldsm4(r4, sB + nrow * 128 + ((c16 ^ (nrow & 7)) << 4));
                b[2 * t][0] = r4[0]; b[2 * t][1] = r4[1];
                b[2 * t + 1][0] = r4[2]; b[2 * t + 1][1] = r4[3];
            }
#pragma unroll
            for (int mt = 0; mt < 4; mt++)
#pragma unroll
                for (int nt = 0; nt < 4; nt++)
                    mma16(acc[mt][nt], a[mt], b[nt]);
        }
    }

    // Epilogue
    const int gr0 = row0 + wm * 64 + (lane >> 2);
    const int gc0 = col0 + wn * 32 + (lane & 3) * 2;
    const float c2 = 0.03125f * 1.4426950408889634f;   // (1/sqrt(1024)) * log2(e)
    const bool partial = (MODE == 1) && (col0 + BN - 1 > row0);

#pragma unroll
    for (int mt = 0; mt < 4; mt++) {
        const int gr = gr0 + mt * 16;
        float inv0 = 1.0f, inv1 = 1.0f;
        if (MODE == 2) {
            inv0 = 1.0f / g_l[(size_t)z * SEQ + gr];
            inv1 = 1.0f / g_l[(size_t)z * SEQ + gr + 8];
        }
#pragma unroll
        for (int nt = 0; nt < 4; nt++) {
            const int gc = gc0 + nt * 8;
            if (MODE == 0) {
                float2 bb = *(const float2*)(bias + gc);
                __half2 h0 = __floats2half2_rn(acc[mt][nt][0] + bb.x,
                                               acc[mt][nt][1] + bb.y);
                __half2 h1 = __floats2half2_rn(acc[mt][nt][2] + bb.x,
                                               acc[mt][nt][3] + bb.y);
                *(__half2*)(Ch + (size_t)gr * ldc + gc)       = h0;
                *(__half2*)(Ch + (size_t)(gr + 8) * ldc + gc) = h1;
            } else if (MODE == 1) {
                float w0 = wexp(acc[mt][nt][0], c2);
                float w1 = wexp(acc[mt][nt][1], c2);
                float w2 = wexp(acc[mt][nt][2], c2);
                float w3 = wexp(acc[mt][nt][3], c2);
                if (partial) {
                    if (gc > gr)         w0 = 0.0f;
                    if (gc + 1 > gr)     w1 = 0.0f;
                    if (gc > gr + 8)     w2 = 0.0f;
                    if (gc + 1 > gr + 8) w3 = 0.0f;
                }
                *(__half2*)(Ch + (size_t)gr * ldc + gc)       = __floats2half2_rn(w0, w1);
                *(__half2*)(Ch + (size_t)(gr + 8) * ldc + gc) = __floats2half2_rn(w2, w3);
            } else {
                float2 o0, o1;
                o0.x = acc[mt][nt][0] * inv0;
                o0.y = acc[mt][nt][1] * inv0;
                o1.x = acc[mt][nt][2] * inv1;
                o1.y = acc[mt][nt][3] * inv1;
                *(float2*)(Cf + (size_t)gr * ldc + gc)       = o0;
                *(float2*)(Cf + (size_t)(gr + 8) * ldc + gc) = o1;
            }
        }
    }
}

// ---------------------------------------------------------------------------
// Prep kernels
// ---------------------------------------------------------------------------
__global__ __launch_bounds__(256)
void conv_x_kernel(const float* __restrict__ x)
{
    const int idx = blockIdx.x * 256 + threadIdx.x;   // one float4 each
    float4 v = *(const float4*)(x + (size_t)idx * 4);
    __half2* dst = (__half2*)(g_xh + (size_t)idx * 4);
    dst[0] = __floats2half2_rn(v.x, v.y);
    dst[1] = __floats2half2_rn(v.z, v.w);
}

__global__ __launch_bounds__(256)
void transpose_w_kernel(const float* __restrict__ Wq, const float* __restrict__ Wk,
                        const float* __restrict__ Wv)
{
    __shared__ float t[32][33];
    const int zz = blockIdx.z;
    const float* W = (zz == 0 ? Wq : (zz == 1 ? Wk : Wv));
    const int x0 = blockIdx.x * 32;   // n
    const int y0 = blockIdx.y * 32;   // k
    const int tx = threadIdx.x & 31, ty = threadIdx.x >> 5;
#pragma unroll
    for (int j = 0; j < 4; j++)
        t[ty + j * 8][tx] = W[(size_t)(y0 + ty + j * 8) * DIM + x0 + tx];
    __syncthreads();
    __half* out = g_wth + (size_t)zz * DIM * DIM;
#pragma unroll
    for (int j = 0; j < 4; j++)
        out[(size_t)(x0 + ty + j * 8) * DIM + y0 + tx] = __float2half_rn(t[tx][ty + j * 8]);
}

__global__ __launch_bounds__(256)
void transpose_v_kernel()
{
    __shared__ __half t[32][34];
    const int b = blockIdx.z;
    const __half* vsrc = g_vh + (size_t)b * SEQ * DIM;
    __half* vdst = g_vth + (size_t)b * DIM * SEQ;
    const int x0 = blockIdx.x * 32;   // d
    const int y0 = blockIdx.y * 32;   // s
    const int tx = threadIdx.x & 31, ty = threadIdx.x >> 5;
#pragma unroll
    for (int j = 0; j < 4; j++)
        t[ty + j * 8][tx] = vsrc[(size_t)(y0 + ty + j * 8) * DIM + x0 + tx];
    __syncthreads();
#pragma unroll
    for (int j = 0; j < 4; j++)
        vdst[(size_t)(x0 + ty + j * 8) * SEQ + y0 + tx] = t[tx][ty + j * 8];
}

// ---------------------------------------------------------------------------
// Row sums of the unnormalized fp16 weights: l[row] = sum_{k<=row} w[row][k].
// grid: (SEQ, BATCH), 128 threads.
// ---------------------------------------------------------------------------
__global__ __launch_bounds__(128)
void rowsum_kernel()
{
    const int j = blockIdx.x;
    const int b = blockIdx.y;
    const __half* row = g_sh + ((size_t)b * SEQ + j) * SEQ;
    const int n = j + 1;
    const int n8 = n & ~7;

    __shared__ float red[128];
    const int tid = threadIdx.x;

    float s = 0.0f;
    for (int k = 8 * tid; k < n8; k += 8 * 128) {
        float4 v4 = *(const float4*)(row + k);      // 8 halves
        const __half2* h = (const __half2*)&v4;
#pragma unroll
        for (int t = 0; t < 4; t++) {
            float2 f = __half22float2(h[t]);
            s += f.x + f.y;
        }
    }
    for (int k = n8 + tid; k < n; k += 128)
        s += __half2float(row[k]);

    red[tid] = s;
    __syncthreads();
    for (int st = 64; st > 0; st >>= 1) {
        if (tid < st) red[tid] += red[tid + st];
        __syncthreads();
    }
    if (tid == 0) g_l[b * SEQ + j] = red[0];
}

// ---------------------------------------------------------------------------
extern "C" void kernel_launch(void* const* d_in, const int* in_sizes, int n_in,
                              void* d_out, int out_size)
{
    const float* x  = (const float*)d_in[0];
    const float* Wq = (const float*)d_in[1];
    const float* bq = (const float*)d_in[2];
    const float* Wk = (const float*)d_in[3];
    const float* bk = (const float*)d_in[4];
    const float* Wv = (const float*)d_in[5];
    const float* bv = (const float*)d_in[6];
    float* out = (float*)d_out;

    cudaFuncSetAttribute(gemm_nt<0>, cudaFuncAttributeMaxDynamicSharedMemorySize, SMEM_BYTES);
    cudaFuncSetAttribute(gemm_nt<1>, cudaFuncAttributeMaxDynamicSharedMemorySize, SMEM_BYTES);
    cudaFuncSetAttribute(gemm_nt<2>, cudaFuncAttributeMaxDynamicSharedMemorySize, SMEM_BYTES);

    // prep
    conv_x_kernel<<<MTOT * DIM / (256 * 4), 256>>>(x);
    {
        dim3 g(DIM / 32, DIM / 32, 3);
        transpose_w_kernel<<<g, 256>>>(Wq, Wk, Wv);
    }
    // QKV
    {
        dim3 g(DIM / BN, MTOT / BM, 3);
        gemm_nt<0><<<g, NTHR_G, SMEM_BYTES>>>(nullptr, bq, bk, bv);
    }
    // v^T
    {
        dim3 g(DIM / 32, SEQ / 32, BATCH);
        transpose_v_kernel<<<g, 256>>>();
    }
    // scores -> unnormalized exp weights (fp16) with causal mask
    {
        dim3 g(SEQ / BN, SEQ / BM, BATCH);
        gemm_nt<1><<<g, NTHR_G, SMEM_BYTES>>>(nullptr, nullptr, nullptr, nullptr);
    }
    // row sums
    {
        dim3 g(SEQ, BATCH);
        rowsum_kernel<<<g, 128>>>();
    }
    // PV with 1/l scaling in epilogue
    {
        dim3 g(DIM / BN, SEQ / BM, BATCH);
        gemm_nt<2><<<g, NTHR_G, SMEM_BYTES>>>(out, nullptr, nullptr, nullptr);
    }
}

// round 11
// speedup vs baseline: 1.1569x; 1.1569x over previous
#include <cuda_runtime.h>
#include <cuda_fp16.h>
#include <math.h>
#include <stdint.h>

// ---------------------------------------------------------------------------
// Problem constants
// ---------------------------------------------------------------------------
#define BATCH 4
#define SEQ   4096
#define DIM   1024
#define MTOT  (BATCH * SEQ)     // 16384

#define NTHR_G 256              // 8 warps per GEMM CTA (2x4 grid of 64x32 tiles)
#define STAGES 3
#define BK     64               // halves per k-chunk (128 B per row)
#define TILE_B  16384           // 128 rows x 128 bytes
#define STAGE_B (2 * TILE_B)
#define SMEM_BYTES (STAGES * STAGE_B)   // 98304 (2 CTAs/SM)

// ---------------------------------------------------------------------------
// Scratch (__device__ globals: allocation-free rule)
// ---------------------------------------------------------------------------
__device__ __half g_xh[MTOT * DIM];                  // fp16 x
__device__ __half g_wth[3 * DIM * DIM];              // W^T fp16 (q,k,v)
__device__ __half g_qh[MTOT * DIM];
__device__ __half g_kh[MTOT * DIM];
__device__ __half g_vh[MTOT * DIM];
__device__ __half g_vth[(size_t)BATCH * DIM * SEQ];  // v^T fp16
__device__ __half g_sh[(size_t)BATCH * SEQ * SEQ];   // UNNORMALIZED exp weights fp16
__device__ float  g_l[MTOT];                         // per-row weight sums

// ---------------------------------------------------------------------------
// Helpers
// ---------------------------------------------------------------------------
__device__ __forceinline__ uint32_t smem_u32(const void* p) {
    return (uint32_t)__cvta_generic_to_shared(p);
}

__device__ __forceinline__ void cp16(uint32_t dst, const void* src) {
    asm volatile("cp.async.cg.shared.global [%0], [%1], 16;\n" :: "r"(dst), "l"(src));
}
#define CP_COMMIT() asm volatile("cp.async.commit_group;\n")
#define CP_WAIT1()  asm volatile("cp.async.wait_group 1;\n")
#define CP_WAIT0()  asm volatile("cp.async.wait_group 0;\n")

__device__ __forceinline__ void ldsm4(uint32_t* r, uint32_t addr) {
    asm volatile("ldmatrix.sync.aligned.m8n8.x4.shared.b16 {%0,%1,%2,%3}, [%4];"
                 : "=r"(r[0]), "=r"(r[1]), "=r"(r[2]), "=r"(r[3]) : "r"(addr));
}

__device__ __forceinline__ void mma16(float* d, const uint32_t* a, const uint32_t* b) {
    asm volatile(
        "mma.sync.aligned.m16n8k16.row.col.f32.f16.f16.f32 "
        "{%0,%1,%2,%3}, {%4,%5,%6,%7}, {%8,%9}, {%0,%1,%2,%3};\n"
        : "+f"(d[0]), "+f"(d[1]), "+f"(d[2]), "+f"(d[3])
        : "r"(a[0]), "r"(a[1]), "r"(a[2]), "r"(a[3]), "r"(b[0]), "r"(b[1]));
}

// exp2 with clamp: keeps fp16 finite even for pathological scores
__device__ __forceinline__ float wexp(float s, float c2) {
    return exp2f(fminf(s * c2, 15.0f));
}

// ---------------------------------------------------------------------------
// Tile fill: 128 rows x 64 halves (128B/row), swizzled chunk = c16 ^ (r&7).
// 256 threads, 4 chunks each.
// ---------------------------------------------------------------------------
__device__ __forceinline__ void fill_tile(uint32_t sdst, const __half* __restrict__ g,
                                          int ld, int k0) {
    const int tid = threadIdx.x;
#pragma unroll
    for (int i = 0; i < 4; i++) {
        int c = tid + i * 256;
        int r = c >> 3, c16 = c & 7;
        cp16(sdst + r * 128 + ((c16 ^ (r & 7)) << 4),
             g + (size_t)r * ld + k0 + c16 * 8);
    }
}

// ---------------------------------------------------------------------------
// Unified NT fp16 GEMM: C[128x128] = A(row-major,K-contig) . B^T(K-contig rows)
// 8 warps (2x4 grid), warp tile 64x32, m16n8k16, 3-stage cp.async pipeline,
// one barrier per K-iter. (R8 config: 2 CTAs/SM — do not reduce.)
// MODE 0: QKV    A=g_xh,  B=g_wth[z], C=g_qh/g_kh/g_vh (+bias fp32, ->fp16)
// MODE 1: scores A=g_qh[z],B=g_kh[z], C=g_sh: w = exp2(s*c2) fp16, causal
//                mask, AND fused row-sum accumulation into g_l (atomics)
// MODE 2: PV     A=g_sh[z],B=g_vth[z],C=out fp32 scaled by 1/g_l[row]
// ---------------------------------------------------------------------------
template <int MODE>
__global__ __launch_bounds__(NTHR_G, 2)
void gemm_nt(float* __restrict__ Cout,
             const float* __restrict__ b0, const float* __restrict__ b1,
             const float* __restrict__ b2)
{
    const int row0 = blockIdx.y * 128;
    const int col0 = blockIdx.x * 128;
    const int z = blockIdx.z;
    if (MODE == 1 && col0 > row0) return;

    const __half *A, *B;
    const float* bias = nullptr;
    __half* Ch = nullptr;
    float* Cf = nullptr;
    int lda, ldb, ldc, nK;
    if (MODE == 0) {
        A = g_xh; lda = DIM;
        B = g_wth + (size_t)z * DIM * DIM; ldb = DIM;
        Ch = (z == 0 ? g_qh : (z == 1 ? g_kh : g_vh)); ldc = DIM;
        bias = (z == 0 ? b0 : (z == 1 ? b1 : b2));
        nK = DIM / BK;
    } else if (MODE == 1) {
        A = g_qh + (size_t)z * SEQ * DIM; lda = DIM;
        B = g_kh + (size_t)z * SEQ * DIM; ldb = DIM;
        Ch = g_sh + (size_t)z * SEQ * SEQ; ldc = SEQ;
        nK = DIM / BK;
    } else {
        A = g_sh + (size_t)z * SEQ * SEQ; lda = SEQ;
        B = g_vth + (size_t)z * DIM * SEQ; ldb = SEQ;
        Cf = Cout + (size_t)z * SEQ * DIM; ldc = DIM;
        nK = (row0 + 128) / BK;
    }
    const __half* Arow = A + (size_t)row0 * lda;
    const __half* Brow = B + (size_t)col0 * ldb;

    extern __shared__ char smem[];
    __shared__ float sred[128];   // MODE 1 row-sum reduction buffer
    const uint32_t sbase = smem_u32(smem);

    const int tid  = threadIdx.x;
    const int lane = tid & 31, warp = tid >> 5;
    const int wm = warp & 1, wn = warp >> 1;      // 2x4 warp grid: 64x32 tiles
    const int mat = lane >> 3, rl = lane & 7;     // ldmatrix address lanes

    float acc[4][4][4];
#pragma unroll
    for (int i = 0; i < 4; i++)
#pragma unroll
        for (int j = 0; j < 4; j++)
#pragma unroll
            for (int t = 0; t < 4; t++) acc[i][j][t] = 0.0f;

    if (MODE == 1) {
        if (tid < 128) sred[tid] = 0.0f;
    }

    // prologue: stages 0 and 1
    fill_tile(sbase, Arow, lda, 0);
    fill_tile(sbase + TILE_B, Brow, ldb, 0);
    CP_COMMIT();
    fill_tile(sbase + STAGE_B, Arow, lda, BK);
    fill_tile(sbase + STAGE_B + TILE_B, Brow, ldb, BK);
    CP_COMMIT();

    for (int it = 0; it < nK; ++it) {
        if (it + 1 < nK) { CP_WAIT1(); } else { CP_WAIT0(); }
        __syncthreads();
        // Barrier proves all warps finished reading stage (it-1), so the
        // prefetch into slot (it+2)%3 == (it-1)%3 is safe: one barrier/iter.
        if (it + 2 < nK) {
            const int slot = (it + 2) % STAGES;
            fill_tile(sbase + slot * STAGE_B, Arow, lda, (it + 2) * BK);
            fill_tile(sbase + slot * STAGE_B + TILE_B, Brow, ldb, (it + 2) * BK);
            CP_COMMIT();
        }

        const uint32_t sA = sbase + (it % STAGES) * STAGE_B;
        const uint32_t sB = sA + TILE_B;

#pragma unroll
        for (int kk = 0; kk < 4; kk++) {          // 4 x k16 per BK=64
            const int klo = kk * 2;               // 16B chunk index

            uint32_t a[4][4];
#pragma unroll
            for (int mt = 0; mt < 4; mt++) {
                int row = wm * 64 + mt * 16 + ((mat & 1) << 3) + rl;
                int c16 = klo + (mat >> 1);
                ldsm4(a[mt], sA + row * 128 + ((c16 ^ (row & 7)) << 4));
            }
            uint32_t b[4][2];
#pragma unroll
            for (int t = 0; t < 2; t++) {
                int nrow = wn * 32 + t * 16 + ((mat >> 1) << 3) + rl;
                int c16 = klo + (mat & 1);
                uint32_t r4[4];
                ldsm4(r4, sB + nrow * 128 + ((c16 ^ (nrow & 7)) << 4));
                b[2 * t][0] = r4[0]; b[2 * t][1] = r4[1];
                b[2 * t + 1][0] = r4[2]; b[2 * t + 1][1] = r4[3];
            }
#pragma unroll
            for (int mt = 0; mt < 4; mt++)
#pragma unroll
                for (int nt = 0; nt < 4; nt++)
                    mma16(acc[mt][nt], a[mt], b[nt]);
        }
    }

    // Epilogue
    const int gr0 = row0 + wm * 64 + (lane >> 2);
    const int gc0 = col0 + wn * 32 + (lane & 3) * 2;
    const float c2 = 0.03125f * 1.4426950408889634f;   // (1/sqrt(1024)) * log2(e)
    const bool diag = (MODE == 1) && (col0 == row0);

#pragma unroll
    for (int mt = 0; mt < 4; mt++) {
        const int gr = gr0 + mt * 16;
        float inv0 = 1.0f, inv1 = 1.0f;
        if (MODE == 2) {
            inv0 = 1.0f / g_l[(size_t)z * SEQ + gr];
            inv1 = 1.0f / g_l[(size_t)z * SEQ + gr + 8];
        }
        float rs0 = 0.0f, rs1 = 0.0f;   // MODE 1: row sums for gr, gr+8
#pragma unroll
        for (int nt = 0; nt < 4; nt++) {
            const int gc = gc0 + nt * 8;
            if (MODE == 0) {
                float2 bb = *(const float2*)(bias + gc);
                __half2 h0 = __floats2half2_rn(acc[mt][nt][0] + bb.x,
                                               acc[mt][nt][1] + bb.y);
                __half2 h1 = __floats2half2_rn(acc[mt][nt][2] + bb.x,
                                               acc[mt][nt][3] + bb.y);
                *(__half2*)(Ch + (size_t)gr * ldc + gc)       = h0;
                *(__half2*)(Ch + (size_t)(gr + 8) * ldc + gc) = h1;
            } else if (MODE == 1) {
                float w0 = wexp(acc[mt][nt][0], c2);
                float w1 = wexp(acc[mt][nt][1], c2);
                float w2 = wexp(acc[mt][nt][2], c2);
                float w3 = wexp(acc[mt][nt][3], c2);
                if (diag) {
                    if (gc > gr)         w0 = 0.0f;
                    if (gc + 1 > gr)     w1 = 0.0f;
                    if (gc > gr + 8)     w2 = 0.0f;
                    if (gc + 1 > gr + 8) w3 = 0.0f;
                }
                rs0 += w0 + w1;
                rs1 += w2 + w3;
                *(__half2*)(Ch + (size_t)gr * ldc + gc)       = __floats2half2_rn(w0, w1);
                *(__half2*)(Ch + (size_t)(gr + 8) * ldc + gc) = __floats2half2_rn(w2, w3);
            } else {
                float2 o0, o1;
                o0.x = acc[mt][nt][0] * inv0;
                o0.y = acc[mt][nt][1] * inv0;
                o1.x = acc[mt][nt][2] * inv1;
                o1.y = acc[mt][nt][3] * inv1;
                *(float2*)(Cf + (size_t)gr * ldc + gc)       = o0;
                *(float2*)(Cf + (size_t)(gr + 8) * ldc + gc) = o1;
            }
        }
        if (MODE == 1) {
            // quad-lane reduce: lanes differing in (lane&3) share the row
            rs0 += __shfl_xor_sync(0xffffffffu, rs0, 1);
            rs0 += __shfl_xor_sync(0xffffffffu, rs0, 2);
            rs1 += __shfl_xor_sync(0xffffffffu, rs1, 1);
            rs1 += __shfl_xor_sync(0xffffffffu, rs1, 2);
            if ((lane & 3) == 0) {
                atomicAdd(&sred[gr - row0], rs0);
                atomicAdd(&sred[gr + 8 - row0], rs1);
            }
        }
    }

    if (MODE == 1) {
        __syncthreads();
        if (tid < 128)
            atomicAdd(&g_l[(size_t)z * SEQ + row0 + tid], sred[tid]);
    }
}

// ---------------------------------------------------------------------------
// Prep kernels
// ---------------------------------------------------------------------------
__global__ __launch_bounds__(256)
void conv_x_kernel(const float* __restrict__ x)
{
    const int idx = blockIdx.x * 256 + threadIdx.x;   // one float4 each
    float4 v = *(const float4*)(x + (size_t)idx * 4);
    __half2* dst = (__half2*)(g_xh + (size_t)idx * 4);
    dst[0] = __floats2half2_rn(v.x, v.y);
    dst[1] = __floats2half2_rn(v.z, v.w);
}

__global__ __launch_bounds__(256)
void transpose_w_kernel(const float* __restrict__ Wq, const float* __restrict__ Wk,
                        const float* __restrict__ Wv)
{
    __shared__ float t[32][33];
    const int zz = blockIdx.z;
    const float* W = (zz == 0 ? Wq : (zz == 1 ? Wk : Wv));
    const int x0 = blockIdx.x * 32;   // n
    const int y0 = blockIdx.y * 32;   // k
    const int tx = threadIdx.x & 31, ty = threadIdx.x >> 5;
#pragma unroll
    for (int j = 0; j < 4; j++)
        t[ty + j * 8][tx] = W[(size_t)(y0 + ty + j * 8) * DIM + x0 + tx];
    __syncthreads();
    __half* out = g_wth + (size_t)zz * DIM * DIM;
#pragma unroll
    for (int j = 0; j < 4; j++)
        out[(size_t)(x0 + ty + j * 8) * DIM + y0 + tx] = __float2half_rn(t[tx][ty + j * 8]);
}

__global__ __launch_bounds__(256)
void transpose_v_kernel()
{
    __shared__ __half t[32][34];
    const int b = blockIdx.z;
    const __half* vsrc = g_vh + (size_t)b * SEQ * DIM;
    __half* vdst = g_vth + (size_t)b * DIM * SEQ;
    const int x0 = blockIdx.x * 32;   // d
    const int y0 = blockIdx.y * 32;   // s
    const int tx = threadIdx.x & 31, ty = threadIdx.x >> 5;
#pragma unroll
    for (int j = 0; j < 4; j++)
        t[ty + j * 8][tx] = vsrc[(size_t)(y0 + ty + j * 8) * DIM + x0 + tx];
    __syncthreads();
#pragma unroll
    for (int j = 0; j < 4; j++)
        vdst[(size_t)(x0 + ty + j * 8) * SEQ + y0 + tx] = t[tx][ty + j * 8];
}

// ---------------------------------------------------------------------------
extern "C" void kernel_launch(void* const* d_in, const int* in_sizes, int n_in,
                              void* d_out, int out_size)
{
    const float* x  = (const float*)d_in[0];
    const float* Wq = (const float*)d_in[1];
    const float* bq = (const float*)d_in[2];
    const float* Wk = (const float*)d_in[3];
    const float* bk = (const float*)d_in[4];
    const float* Wv = (const float*)d_in[5];
    const float* bv = (const float*)d_in[6];
    float* out = (float*)d_out;

    cudaFuncSetAttribute(gemm_nt<0>, cudaFuncAttributeMaxDynamicSharedMemorySize, SMEM_BYTES);
    cudaFuncSetAttribute(gemm_nt<1>, cudaFuncAttributeMaxDynamicSharedMemorySize, SMEM_BYTES);
    cudaFuncSetAttribute(gemm_nt<2>, cudaFuncAttributeMaxDynamicSharedMemorySize, SMEM_BYTES);

    // zero the row-sum accumulators (graph-capturable memset, no alloc)
    void* lptr = nullptr;
    cudaGetSymbolAddress(&lptr, g_l);
    cudaMemsetAsync(lptr, 0, MTOT * sizeof(float));

    // prep
    conv_x_kernel<<<MTOT * DIM / (256 * 4), 256>>>(x);
    {
        dim3 g(DIM / 32, DIM / 32, 3);
        transpose_w_kernel<<<g, 256>>>(Wq, Wk, Wv);
    }
    // QKV
    {
        dim3 g(DIM / 128, MTOT / 128, 3);
        gemm_nt<0><<<g, NTHR_G, SMEM_BYTES>>>(nullptr, bq, bk, bv);
    }
    // v^T
    {
        dim3 g(DIM / 32, SEQ / 32, BATCH);
        transpose_v_kernel<<<g, 256>>>();
    }
    // scores -> unnormalized exp weights (fp16) + fused row sums
    {
        dim3 g(SEQ / 128, SEQ / 128, BATCH);
        gemm_nt<1><<<g, NTHR_G, SMEM_BYTES>>>(nullptr, nullptr, nullptr, nullptr);
    }
    // PV with 1/l scaling in epilogue
    {
        dim3 g(DIM / 128, SEQ / 128, BATCH);
        gemm_nt<2><<<g, NTHR_G, SMEM_BYTES>>>(out, nullptr, nullptr, nullptr);
    }
}

// round 15
// speedup vs baseline: 1.1725x; 1.0134x over previous
#include <cuda_runtime.h>
#include <cuda_fp16.h>
#include <math.h>
#include <stdint.h>

// ---------------------------------------------------------------------------
// Problem constants
// ---------------------------------------------------------------------------
#define BATCH 4
#define SEQ   4096
#define DIM   1024
#define MTOT  (BATCH * SEQ)     // 16384

#define NTHR_G 256              // 8 warps per GEMM CTA (2x4 grid of 64x32 tiles)
#define STAGES 3
#define BK     64               // halves per k-chunk (128 B per row)
#define TILE_B  16384           // 128 rows x 128 bytes
#define STAGE_B (2 * TILE_B)
#define SMEM_BYTES (STAGES * STAGE_B)   // 98304 (2 CTAs/SM)

// transpose staging: 128 x 136 halves (pad 8 -> conflict-free column walks)
#define TPAD 136

// ---------------------------------------------------------------------------
// Scratch (__device__ globals: allocation-free rule)
// ---------------------------------------------------------------------------
__device__ __half g_xh[MTOT * DIM];                  // fp16 x
__device__ __half g_wth[3 * DIM * DIM];              // W^T fp16 (q,k,v)
__device__ __half g_qh[MTOT * DIM];
__device__ __half g_kh[MTOT * DIM];
__device__ __half g_vth[(size_t)BATCH * DIM * SEQ];  // v^T fp16 (written by QKV z=2)
__device__ __half g_sh[(size_t)BATCH * SEQ * SEQ];   // UNNORMALIZED exp weights fp16
__device__ float  g_l[MTOT];                         // per-row weight sums

// ---------------------------------------------------------------------------
// Helpers
// ---------------------------------------------------------------------------
__device__ __forceinline__ uint32_t smem_u32(const void* p) {
    return (uint32_t)__cvta_generic_to_shared(p);
}

__device__ __forceinline__ void cp16(uint32_t dst, const void* src) {
    asm volatile("cp.async.cg.shared.global [%0], [%1], 16;\n" :: "r"(dst), "l"(src));
}
#define CP_COMMIT() asm volatile("cp.async.commit_group;\n")
#define CP_WAIT1()  asm volatile("cp.async.wait_group 1;\n")
#define CP_WAIT0()  asm volatile("cp.async.wait_group 0;\n")

__device__ __forceinline__ void ldsm4(uint32_t* r, uint32_t addr) {
    asm volatile("ldmatrix.sync.aligned.m8n8.x4.shared.b16 {%0,%1,%2,%3}, [%4];"
                 : "=r"(r[0]), "=r"(r[1]), "=r"(r[2]), "=r"(r[3]) : "r"(addr));
}

__device__ __forceinline__ void mma16(float* d, const uint32_t* a, const uint32_t* b) {
    asm volatile(
        "mma.sync.aligned.m16n8k16.row.col.f32.f16.f16.f32 "
        "{%0,%1,%2,%3}, {%4,%5,%6,%7}, {%8,%9}, {%0,%1,%2,%3};\n"
        : "+f"(d[0]), "+f"(d[1]), "+f"(d[2]), "+f"(d[3])
        : "r"(a[0]), "r"(a[1]), "r"(a[2]), "r"(a[3]), "r"(b[0]), "r"(b[1]));
}

// exp2 with clamp: keeps fp16 finite even for pathological scores
__device__ __forceinline__ float wexp(float s, float c2) {
    return exp2f(fminf(s * c2, 15.0f));
}

// ---------------------------------------------------------------------------
// Tile fill: 128 rows x 64 halves (128B/row), swizzled chunk = c16 ^ (r&7).
// 256 threads, 4 chunks each.
// ---------------------------------------------------------------------------
__device__ __forceinline__ void fill_tile(uint32_t sdst, const __half* __restrict__ g,
                                          int ld, int k0) {
    const int tid = threadIdx.x;
#pragma unroll
    for (int i = 0; i < 4; i++) {
        int c = tid + i * 256;
        int r = c >> 3, c16 = c & 7;
        cp16(sdst + r * 128 + ((c16 ^ (r & 7)) << 4),
             g + (size_t)r * ld + k0 + c16 * 8);
    }
}

// ---------------------------------------------------------------------------
// Unified NT fp16 GEMM: C[128x128] = A(row-major,K-contig) . B^T(K-contig rows)
// 8 warps (2x4 grid), warp tile 64x32, m16n8k16, 3-stage cp.async pipeline,
// one barrier per K-iter. (R8 config: 2 CTAs/SM — do not reduce.)
// MODE 0: QKV    A=g_xh, B=g_wth[z]. z=0/1 -> g_qh/g_kh row-major (+bias).
//                z=2 -> v^T written DIRECTLY to g_vth via smem-staged
//                in-tile transpose (+bias before transpose).
// MODE 1: scores A=g_qh[z],B=g_kh[z], C=g_sh: w = exp2(s*c2) fp16, causal
//                mask, AND fused row-sum accumulation into g_l (atomics)
// MODE 2: PV     A=g_sh[z],B=g_vth[z],C=out fp32 scaled by 1/g_l[row]
// ---------------------------------------------------------------------------
template <int MODE>
__global__ __launch_bounds__(NTHR_G, 2)
void gemm_nt(float* __restrict__ Cout,
             const float* __restrict__ b0, const float* __restrict__ b1,
             const float* __restrict__ b2)
{
    const int row0 = blockIdx.y * 128;
    const int col0 = blockIdx.x * 128;
    const int z = blockIdx.z;
    if (MODE == 1 && col0 > row0) return;

    const __half *A, *B;
    const float* bias = nullptr;
    __half* Ch = nullptr;
    float* Cf = nullptr;
    int lda, ldb, ldc, nK;
    if (MODE == 0) {
        A = g_xh; lda = DIM;
        B = g_wth + (size_t)z * DIM * DIM; ldb = DIM;
        Ch = (z == 0 ? g_qh : (z == 1 ? g_kh : nullptr)); ldc = DIM;
        bias = (z == 0 ? b0 : (z == 1 ? b1 : b2));
        nK = DIM / BK;
    } else if (MODE == 1) {
        A = g_qh + (size_t)z * SEQ * DIM; lda = DIM;
        B = g_kh + (size_t)z * SEQ * DIM; ldb = DIM;
        Ch = g_sh + (size_t)z * SEQ * SEQ; ldc = SEQ;
        nK = DIM / BK;
    } else {
        A = g_sh + (size_t)z * SEQ * SEQ; lda = SEQ;
        B = g_vth + (size_t)z * DIM * SEQ; ldb = SEQ;
        Cf = Cout + (size_t)z * SEQ * DIM; ldc = DIM;
        nK = (row0 + 128) / BK;
    }
    const __half* Arow = A + (size_t)row0 * lda;
    const __half* Brow = B + (size_t)col0 * ldb;

    extern __shared__ char smem[];
    __shared__ float sred[128];   // MODE 1 row-sum reduction buffer
    const uint32_t sbase = smem_u32(smem);

    const int tid  = threadIdx.x;
    const int lane = tid & 31, warp = tid >> 5;
    const int wm = warp & 1, wn = warp >> 1;      // 2x4 warp grid: 64x32 tiles
    const int mat = lane >> 3, rl = lane & 7;     // ldmatrix address lanes

    float acc[4][4][4];
#pragma unroll
    for (int i = 0; i < 4; i++)
#pragma unroll
        for (int j = 0; j < 4; j++)
#pragma unroll
            for (int t = 0; t < 4; t++) acc[i][j][t] = 0.0f;

    if (MODE == 1) {
        if (tid < 128) sred[tid] = 0.0f;
    }

    // prologue: stages 0 and 1
    fill_tile(sbase, Arow, lda, 0);
    fill_tile(sbase + TILE_B, Brow, ldb, 0);
    CP_COMMIT();
    fill_tile(sbase + STAGE_B, Arow, lda, BK);
    fill_tile(sbase + STAGE_B + TILE_B, Brow, ldb, BK);
    CP_COMMIT();

    for (int it = 0; it < nK; ++it) {
        if (it + 1 < nK) { CP_WAIT1(); } else { CP_WAIT0(); }
        __syncthreads();
        // Barrier proves all warps finished reading stage (it-1), so the
        // prefetch into slot (it+2)%3 == (it-1)%3 is safe: one barrier/iter.
        if (it + 2 < nK) {
            const int slot = (it + 2) % STAGES;
            fill_tile(sbase + slot * STAGE_B, Arow, lda, (it + 2) * BK);
            fill_tile(sbase + slot * STAGE_B + TILE_B, Brow, ldb, (it + 2) * BK);
            CP_COMMIT();
        }

        const uint32_t sA = sbase + (it % STAGES) * STAGE_B;
        const uint32_t sB = sA + TILE_B;

#pragma unroll
        for (int kk = 0; kk < 4; kk++) {          // 4 x k16 per BK=64
            const int klo = kk * 2;               // 16B chunk index

            uint32_t a[4][4];
#pragma unroll
            for (int mt = 0; mt < 4; mt++) {
                int row = wm * 64 + mt * 16 + ((mat & 1) << 3) + rl;
                int c16 = klo + (mat >> 1);
                ldsm4(a[mt], sA + row * 128 + ((c16 ^ (row & 7)) << 4));
            }
            uint32_t b[4][2];
#pragma unroll
            for (int t = 0; t < 2; t++) {
                int nrow = wn * 32 + t * 16 + ((mat >> 1) << 3) + rl;
                int c16 = klo + (mat & 1);
                uint32_t r4[4];
                ldsm4(r4, sB + nrow * 128 + ((c16 ^ (nrow & 7)) << 4));
                b[2 * t][0] = r4[0]; b[2 * t][1] = r4[1];
                b[2 * t + 1][0] = r4[2]; b[2 * t + 1][1] = r4[3];
            }
#pragma unroll
            for (int mt = 0; mt < 4; mt++)
#pragma unroll
                for (int nt = 0; nt < 4; nt++)
                    mma16(acc[mt][nt], a[mt], b[nt]);
        }
    }

    // Epilogue
    const int gr0 = row0 + wm * 64 + (lane >> 2);
    const int gc0 = col0 + wn * 32 + (lane & 3) * 2;
    const float c2 = 0.03125f * 1.4426950408889634f;   // (1/sqrt(1024)) * log2(e)
    const bool diag = (MODE == 1) && (col0 == row0);

    if (MODE == 0 && z == 2) {
        // v path: add bias, stage tile [m][n] in smem, write transposed g_vth.
        __syncthreads();   // pipeline smem is dead; safe to reuse
        __half* st = (__half*)smem;   // [128][TPAD]
        const int lm0 = wm * 64 + (lane >> 2);
        const int ln0 = wn * 32 + (lane & 3) * 2;
#pragma unroll
        for (int mt = 0; mt < 4; mt++) {
            const int lm = lm0 + mt * 16;
#pragma unroll
            for (int nt = 0; nt < 4; nt++) {
                const int ln = ln0 + nt * 8;
                float2 bb = *(const float2*)(bias + col0 + ln);
                *(__half2*)(st + lm * TPAD + ln) =
                    __floats2half2_rn(acc[mt][nt][0] + bb.x, acc[mt][nt][1] + bb.y);
                *(__half2*)(st + (lm + 8) * TPAD + ln) =
                    __floats2half2_rn(acc[mt][nt][2] + bb.x, acc[mt][nt][3] + bb.y);
            }
        }
        __syncthreads();
        // write transposed: d-row = col0+n, s-cols = row0..row0+127.
        // 256 threads: 2 threads per n (each 64 halves = 128B, coalesced).
        const int n = tid >> 1;               // 0..127
        const int mhalf = (tid & 1) * 64;     // 0 or 64
        const int bz = row0 / SEQ;            // batch from global row
        const size_t srow = (size_t)(row0 - bz * SEQ);
        __half* orow = g_vth + (size_t)bz * DIM * SEQ + (size_t)(col0 + n) * SEQ
                       + srow + mhalf;
#pragma unroll
        for (int i = 0; i < 64; i += 8) {
            __half tmp[8];
#pragma unroll
            for (int u = 0; u < 8; u++) tmp[u] = st[(mhalf + i + u) * TPAD + n];
            *(float4*)(orow + i) = *(float4*)tmp;
        }
    } else {
#pragma unroll
        for (int mt = 0; mt < 4; mt++) {
            const int gr = gr0 + mt * 16;
            float inv0 = 1.0f, inv1 = 1.0f;
            if (MODE == 2) {
                inv0 = __frcp_rn(g_l[(size_t)z * SEQ + gr]);
                inv1 = __frcp_rn(g_l[(size_t)z * SEQ + gr + 8]);
            }
            float rs0 = 0.0f, rs1 = 0.0f;   // MODE 1: row sums for gr, gr+8
#pragma unroll
            for (int nt = 0; nt < 4; nt++) {
                const int gc = gc0 + nt * 8;
                if (MODE == 0) {
                    float2 bb = *(const float2*)(bias + gc);
                    __half2 h0 = __floats2half2_rn(acc[mt][nt][0] + bb.x,
                                                   acc[mt][nt][1] + bb.y);
                    __half2 h1 = __floats2half2_rn(acc[mt][nt][2] + bb.x,
                                                   acc[mt][nt][3] + bb.y);
                    *(__half2*)(Ch + (size_t)gr * ldc + gc)       = h0;
                    *(__half2*)(Ch + (size_t)(gr + 8) * ldc + gc) = h1;
                } else if (MODE == 1) {
                    float w0 = wexp(acc[mt][nt][0], c2);
                    float w1 = wexp(acc[mt][nt][1], c2);
                    float w2 = wexp(acc[mt][nt][2], c2);
                    float w3 = wexp(acc[mt][nt][3], c2);
                    if (diag) {
                        if (gc > gr)         w0 = 0.0f;
                        if (gc + 1 > gr)     w1 = 0.0f;
                        if (gc > gr + 8)     w2 = 0.0f;
                        if (gc + 1 > gr + 8) w3 = 0.0f;
                    }
                    rs0 += w0 + w1;
                    rs1 += w2 + w3;
                    *(__half2*)(Ch + (size_t)gr * ldc + gc)       = __floats2half2_rn(w0, w1);
                    *(__half2*)(Ch + (size_t)(gr + 8) * ldc + gc) = __floats2half2_rn(w2, w3);
                } else {
                    float2 o0, o1;
                    o0.x = acc[mt][nt][0] * inv0;
                    o0.y = acc[mt][nt][1] * inv0;
                    o1.x = acc[mt][nt][2] * inv1;
                    o1.y = acc[mt][nt][3] * inv1;
                    *(float2*)(Cf + (size_t)gr * ldc + gc)       = o0;
                    *(float2*)(Cf + (size_t)(gr + 8) * ldc + gc) = o1;
                }
            }
            if (MODE == 1) {
                // quad-lane reduce: lanes differing in (lane&3) share the row
                rs0 += __shfl_xor_sync(0xffffffffu, rs0, 1);
                rs0 += __shfl_xor_sync(0xffffffffu, rs0, 2);
                rs1 += __shfl_xor_sync(0xffffffffu, rs1, 1);
                rs1 += __shfl_xor_sync(0xffffffffu, rs1, 2);
                if ((lane & 3) == 0) {
                    atomicAdd(&sred[gr - row0], rs0);
                    atomicAdd(&sred[gr + 8 - row0], rs1);
                }
            }
        }
        if (MODE == 1) {
            __syncthreads();
            if (tid < 128)
                atomicAdd(&g_l[(size_t)z * SEQ + row0 + tid], sred[tid]);
        }
    }
}

// ---------------------------------------------------------------------------
// Prep kernels
// ---------------------------------------------------------------------------
__global__ __launch_bounds__(256)
void conv_x_kernel(const float* __restrict__ x)
{
    const int idx = blockIdx.x * 256 + threadIdx.x;   // one float4 each
    float4 v = *(const float4*)(x + (size_t)idx * 4);
    __half2* dst = (__half2*)(g_xh + (size_t)idx * 4);
    dst[0] = __floats2half2_rn(v.x, v.y);
    dst[1] = __floats2half2_rn(v.z, v.w);
}

__global__ __launch_bounds__(256)
void transpose_w_kernel(const float* __restrict__ Wq, const float* __restrict__ Wk,
                        const float* __restrict__ Wv)
{
    __shared__ float t[32][33];
    const int zz = blockIdx.z;
    const float* W = (zz == 0 ? Wq : (zz == 1 ? Wk : Wv));
    const int x0 = blockIdx.x * 32;   // n
    const int y0 = blockIdx.y * 32;   // k
    const int tx = threadIdx.x & 31, ty = threadIdx.x >> 5;
#pragma unroll
    for (int j = 0; j < 4; j++)
        t[ty + j * 8][tx] = W[(size_t)(y0 + ty + j * 8) * DIM + x0 + tx];
    __syncthreads();
    __half* out = g_wth + (size_t)zz * DIM * DIM;
#pragma unroll
    for (int j = 0; j < 4; j++)
        out[(size_t)(x0 + ty + j * 8) * DIM + y0 + tx] = __float2half_rn(t[tx][ty + j * 8]);
}

// ---------------------------------------------------------------------------
extern "C" void kernel_launch(void* const* d_in, const int* in_sizes, int n_in,
                              void* d_out, int out_size)
{
    const float* x  = (const float*)d_in[0];
    const float* Wq = (const float*)d_in[1];
    const float* bq = (const float*)d_in[2];
    const float* Wk = (const float*)d_in[3];
    const float* bk = (const float*)d_in[4];
    const float* Wv = (const float*)d_in[5];
    const float* bv = (const float*)d_in[6];
    float* out = (float*)d_out;

    cudaFuncSetAttribute(gemm_nt<0>, cudaFuncAttributeMaxDynamicSharedMemorySize, SMEM_BYTES);
    cudaFuncSetAttribute(gemm_nt<1>, cudaFuncAttributeMaxDynamicSharedMemorySize, SMEM_BYTES);
    cudaFuncSetAttribute(gemm_nt<2>, cudaFuncAttributeMaxDynamicSharedMemorySize, SMEM_BYTES);

    // zero the row-sum accumulators (graph-capturable memset, no alloc)
    void* lptr = nullptr;
    cudaGetSymbolAddress(&lptr, g_l);
    cudaMemsetAsync(lptr, 0, MTOT * sizeof(float));

    // prep
    conv_x_kernel<<<MTOT * DIM / (256 * 4), 256>>>(x);
    {
        dim3 g(DIM / 32, DIM / 32, 3);
        transpose_w_kernel<<<g, 256>>>(Wq, Wk, Wv);
    }
    // QKV (z=2 writes v^T directly)
    {
        dim3 g(DIM / 128, MTOT / 128, 3);
        gemm_nt<0><<<g, NTHR_G, SMEM_BYTES>>>(nullptr, bq, bk, bv);
    }
    // scores -> unnormalized exp weights (fp16) + fused row sums
    {
        dim3 g(SEQ / 128, SEQ / 128, BATCH);
        gemm_nt<1><<<g, NTHR_G, SMEM_BYTES>>>(nullptr, nullptr, nullptr, nullptr);
    }
    // PV with 1/l scaling in epilogue
    {
        dim3 g(DIM / 128, SEQ / 128, BATCH);
        gemm_nt<2><<<g, NTHR_G, SMEM_BYTES>>>(out, nullptr, nullptr, nullptr);
    }
}

// round 16
// speedup vs baseline: 1.2183x; 1.0391x over previous
#include <cuda_runtime.h>
#include <cuda_fp16.h>
#include <math.h>
#include <stdint.h>

// ---------------------------------------------------------------------------
// Problem constants
// ---------------------------------------------------------------------------
#define BATCH 4
#define SEQ   4096
#define DIM   1024
#define MTOT  (BATCH * SEQ)     // 16384

#define NTHR_G 256              // 8 warps per GEMM CTA (2x4 grid of 64x32 tiles)
#define STAGES 3
#define BK     64               // halves per k-chunk (128 B per row)
#define TILE_B  16384           // 128 rows x 128 bytes
#define STAGE_B (2 * TILE_B)
#define SMEM_BYTES (STAGES * STAGE_B)   // 98304 (2 CTAs/SM)

// transpose staging: 128 x 136 halves (pad 8 -> conflict-free column walks)
#define TPAD 136

// merged prep kernel split point
#define CONV_BLOCKS (MTOT * DIM / (256 * 4))   // 16384
#define WT_BLOCKS   (3 * (DIM / 32) * (DIM / 32))   // 3072

// ---------------------------------------------------------------------------
// Scratch (__device__ globals: allocation-free rule)
// ---------------------------------------------------------------------------
__device__ __half g_xh[MTOT * DIM];                  // fp16 x
__device__ __half g_wth[3 * DIM * DIM];              // W^T fp16 (q,k,v)
__device__ __half g_qh[MTOT * DIM];
__device__ __half g_kh[MTOT * DIM];
__device__ __half g_vth[(size_t)BATCH * DIM * SEQ];  // v^T fp16 (written by QKV z=2)
__device__ __half g_sh[(size_t)BATCH * SEQ * SEQ];   // UNNORMALIZED exp weights fp16
__device__ float  g_l[MTOT];                         // per-row weight sums

// ---------------------------------------------------------------------------
// Helpers
// ---------------------------------------------------------------------------
__device__ __forceinline__ uint32_t smem_u32(const void* p) {
    return (uint32_t)__cvta_generic_to_shared(p);
}

__device__ __forceinline__ void cp16(uint32_t dst, const void* src) {
    asm volatile("cp.async.cg.shared.global [%0], [%1], 16;\n" :: "r"(dst), "l"(src));
}
#define CP_COMMIT() asm volatile("cp.async.commit_group;\n")
#define CP_WAIT1()  asm volatile("cp.async.wait_group 1;\n")
#define CP_WAIT0()  asm volatile("cp.async.wait_group 0;\n")

__device__ __forceinline__ void ldsm4(uint32_t* r, uint32_t addr) {
    asm volatile("ldmatrix.sync.aligned.m8n8.x4.shared.b16 {%0,%1,%2,%3}, [%4];"
                 : "=r"(r[0]), "=r"(r[1]), "=r"(r[2]), "=r"(r[3]) : "r"(addr));
}

__device__ __forceinline__ void mma16(float* d, const uint32_t* a, const uint32_t* b) {
    asm volatile(
        "mma.sync.aligned.m16n8k16.row.col.f32.f16.f16.f32 "
        "{%0,%1,%2,%3}, {%4,%5,%6,%7}, {%8,%9}, {%0,%1,%2,%3};\n"
        : "+f"(d[0]), "+f"(d[1]), "+f"(d[2]), "+f"(d[3])
        : "r"(a[0]), "r"(a[1]), "r"(a[2]), "r"(a[3]), "r"(b[0]), "r"(b[1]));
}

// exp2 with clamp: keeps fp16 finite even for pathological scores
__device__ __forceinline__ float wexp(float s, float c2) {
    return exp2f(fminf(s * c2, 15.0f));
}

// ---------------------------------------------------------------------------
// Tile fill: 128 rows x 64 halves (128B/row), swizzled chunk = c16 ^ (r&7).
// 256 threads, 4 chunks each.
// ---------------------------------------------------------------------------
__device__ __forceinline__ void fill_tile(uint32_t sdst, const __half* __restrict__ g,
                                          int ld, int k0) {
    const int tid = threadIdx.x;
#pragma unroll
    for (int i = 0; i < 4; i++) {
        int c = tid + i * 256;
        int r = c >> 3, c16 = c & 7;
        cp16(sdst + r * 128 + ((c16 ^ (r & 7)) << 4),
             g + (size_t)r * ld + k0 + c16 * 8);
    }
}

// ---------------------------------------------------------------------------
// Unified NT fp16 GEMM: C[128x128] = A(row-major,K-contig) . B^T(K-contig rows)
// 8 warps (2x4 grid), warp tile 64x32, m16n8k16, 3-stage cp.async pipeline,
// one barrier per K-iter. (R8 config: 2 CTAs/SM — do not reduce.)
// MODE 0: QKV    A=g_xh, B=g_wth[z]. z=0/1 -> g_qh/g_kh row-major (+bias).
//                z=2 -> v^T written DIRECTLY to g_vth via smem-staged
//                in-tile transpose (+bias before transpose).
// MODE 1: scores A=g_qh[z],B=g_kh[z], C=g_sh: w = exp2(s*c2) fp16, causal
//                mask, AND fused row-sum accumulation into g_l (atomics)
// MODE 2: PV     A=g_sh[z],B=g_vth[z],C=out fp32 scaled by 1/g_l[row];
//                blockIdx.y REVERSED (heavy rows first) for tail packing
// ---------------------------------------------------------------------------
template <int MODE>
__global__ __launch_bounds__(NTHR_G, 2)
void gemm_nt(float* __restrict__ Cout,
             const float* __restrict__ b0, const float* __restrict__ b1,
             const float* __restrict__ b2)
{
    const int ybIdx = (MODE == 2) ? (gridDim.y - 1 - blockIdx.y) : blockIdx.y;
    const int row0 = ybIdx * 128;
    const int col0 = blockIdx.x * 128;
    const int z = blockIdx.z;
    if (MODE == 1 && col0 > row0) return;

    const __half *A, *B;
    const float* bias = nullptr;
    __half* Ch = nullptr;
    float* Cf = nullptr;
    int lda, ldb, ldc, nK;
    if (MODE == 0) {
        A = g_xh; lda = DIM;
        B = g_wth + (size_t)z * DIM * DIM; ldb = DIM;
        Ch = (z == 0 ? g_qh : (z == 1 ? g_kh : nullptr)); ldc = DIM;
        bias = (z == 0 ? b0 : (z == 1 ? b1 : b2));
        nK = DIM / BK;
    } else if (MODE == 1) {
        A = g_qh + (size_t)z * SEQ * DIM; lda = DIM;
        B = g_kh + (size_t)z * SEQ * DIM; ldb = DIM;
        Ch = g_sh + (size_t)z * SEQ * SEQ; ldc = SEQ;
        nK = DIM / BK;
    } else {
        A = g_sh + (size_t)z * SEQ * SEQ; lda = SEQ;
        B = g_vth + (size_t)z * DIM * SEQ; ldb = SEQ;
        Cf = Cout + (size_t)z * SEQ * DIM; ldc = DIM;
        nK = (row0 + 128) / BK;
    }
    const __half* Arow = A + (size_t)row0 * lda;
    const __half* Brow = B + (size_t)col0 * ldb;

    extern __shared__ char smem[];
    __shared__ float sred[128];   // MODE 1 row-sum reduction buffer
    const uint32_t sbase = smem_u32(smem);

    const int tid  = threadIdx.x;
    const int lane = tid & 31, warp = tid >> 5;
    const int wm = warp & 1, wn = warp >> 1;      // 2x4 warp grid: 64x32 tiles
    const int mat = lane >> 3, rl = lane & 7;     // ldmatrix address lanes

    float acc[4][4][4];
#pragma unroll
    for (int i = 0; i < 4; i++)
#pragma unroll
        for (int j = 0; j < 4; j++)
#pragma unroll
            for (int t = 0; t < 4; t++) acc[i][j][t] = 0.0f;

    if (MODE == 1) {
        if (tid < 128) sred[tid] = 0.0f;
    }

    // prologue: stages 0 and 1
    fill_tile(sbase, Arow, lda, 0);
    fill_tile(sbase + TILE_B, Brow, ldb, 0);
    CP_COMMIT();
    fill_tile(sbase + STAGE_B, Arow, lda, BK);
    fill_tile(sbase + STAGE_B + TILE_B, Brow, ldb, BK);
    CP_COMMIT();

    for (int it = 0; it < nK; ++it) {
        if (it + 1 < nK) { CP_WAIT1(); } else { CP_WAIT0(); }
        __syncthreads();
        // Barrier proves all warps finished reading stage (it-1), so the
        // prefetch into slot (it+2)%3 == (it-1)%3 is safe: one barrier/iter.
        if (it + 2 < nK) {
            const int slot = (it + 2) % STAGES;
            fill_tile(sbase + slot * STAGE_B, Arow, lda, (it + 2) * BK);
            fill_tile(sbase + slot * STAGE_B + TILE_B, Brow, ldb, (it + 2) * BK);
            CP_COMMIT();
        }

        const uint32_t sA = sbase + (it % STAGES) * STAGE_B;
        const uint32_t sB = sA + TILE_B;

#pragma unroll
        for (int kk = 0; kk < 4; kk++) {          // 4 x k16 per BK=64
            const int klo = kk * 2;               // 16B chunk index

            uint32_t a[4][4];
#pragma unroll
            for (int mt = 0; mt < 4; mt++) {
                int row = wm * 64 + mt * 16 + ((mat & 1) << 3) + rl;
                int c16 = klo + (mat >> 1);
                ldsm4(a[mt], sA + row * 128 + ((c16 ^ (row & 7)) << 4));
            }
            uint32_t b[4][2];
#pragma unroll
            for (int t = 0; t < 2; t++) {
                int nrow = wn * 32 + t * 16 + ((mat >> 1) << 3) + rl;
                int c16 = klo + (mat & 1);
                uint32_t r4[4];
                ldsm4(r4, sB + nrow * 128 + ((c16 ^ (nrow & 7)) << 4));
                b[2 * t][0] = r4[0]; b[2 * t][1] = r4[1];
                b[2 * t + 1][0] = r4[2]; b[2 * t + 1][1] = r4[3];
            }
#pragma unroll
            for (int mt = 0; mt < 4; mt++)
#pragma unroll
                for (int nt = 0; nt < 4; nt++)
                    mma16(acc[mt][nt], a[mt], b[nt]);
        }
    }

    // Epilogue
    const int gr0 = row0 + wm * 64 + (lane >> 2);
    const int gc0 = col0 + wn * 32 + (lane & 3) * 2;
    const float c2 = 0.03125f * 1.4426950408889634f;   // (1/sqrt(1024)) * log2(e)
    const bool diag = (MODE == 1) && (col0 == row0);

    if (MODE == 0 && z == 2) {
        // v path: add bias, stage tile [m][n] in smem, write transposed g_vth.
        __syncthreads();   // pipeline smem is dead; safe to reuse
        __half* st = (__half*)smem;   // [128][TPAD]
        const int lm0 = wm * 64 + (lane >> 2);
        const int ln0 = wn * 32 + (lane & 3) * 2;
#pragma unroll
        for (int mt = 0; mt < 4; mt++) {
            const int lm = lm0 + mt * 16;
#pragma unroll
            for (int nt = 0; nt < 4; nt++) {
                const int ln = ln0 + nt * 8;
                float2 bb = *(const float2*)(bias + col0 + ln);
                *(__half2*)(st + lm * TPAD + ln) =
                    __floats2half2_rn(acc[mt][nt][0] + bb.x, acc[mt][nt][1] + bb.y);
                *(__half2*)(st + (lm + 8) * TPAD + ln) =
                    __floats2half2_rn(acc[mt][nt][2] + bb.x, acc[mt][nt][3] + bb.y);
            }
        }
        __syncthreads();
        // write transposed: d-row = col0+n, s-cols = row0..row0+127.
        // 256 threads: 2 threads per n (each 64 halves = 128B, coalesced).
        const int n = tid >> 1;               // 0..127
        const int mhalf = (tid & 1) * 64;     // 0 or 64
        const int bz = row0 / SEQ;            // batch from global row
        const size_t srow = (size_t)(row0 - bz * SEQ);
        __half* orow = g_vth + (size_t)bz * DIM * SEQ + (size_t)(col0 + n) * SEQ
                       + srow + mhalf;
#pragma unroll
        for (int i = 0; i < 64; i += 8) {
            __half tmp[8];
#pragma unroll
            for (int u = 0; u < 8; u++) tmp[u] = st[(mhalf + i + u) * TPAD + n];
            *(float4*)(orow + i) = *(float4*)tmp;
        }
    } else {
#pragma unroll
        for (int mt = 0; mt < 4; mt++) {
            const int gr = gr0 + mt * 16;
            float inv0 = 1.0f, inv1 = 1.0f;
            if (MODE == 2) {
                inv0 = __frcp_rn(g_l[(size_t)z * SEQ + gr]);
                inv1 = __frcp_rn(g_l[(size_t)z * SEQ + gr + 8]);
            }
            float rs0 = 0.0f, rs1 = 0.0f;   // MODE 1: row sums for gr, gr+8
#pragma unroll
            for (int nt = 0; nt < 4; nt++) {
                const int gc = gc0 + nt * 8;
                if (MODE == 0) {
                    float2 bb = *(const float2*)(bias + gc);
                    __half2 h0 = __floats2half2_rn(acc[mt][nt][0] + bb.x,
                                                   acc[mt][nt][1] + bb.y);
                    __half2 h1 = __floats2half2_rn(acc[mt][nt][2] + bb.x,
                                                   acc[mt][nt][3] + bb.y);
                    *(__half2*)(Ch + (size_t)gr * ldc + gc)       = h0;
                    *(__half2*)(Ch + (size_t)(gr + 8) * ldc + gc) = h1;
                } else if (MODE == 1) {
                    float w0 = wexp(acc[mt][nt][0], c2);
                    float w1 = wexp(acc[mt][nt][1], c2);
                    float w2 = wexp(acc[mt][nt][2], c2);
                    float w3 = wexp(acc[mt][nt][3], c2);
                    if (diag) {
                        if (gc > gr)         w0 = 0.0f;
                        if (gc + 1 > gr)     w1 = 0.0f;
                        if (gc > gr + 8)     w2 = 0.0f;
                        if (gc + 1 > gr + 8) w3 = 0.0f;
                    }
                    rs0 += w0 + w1;
                    rs1 += w2 + w3;
                    *(__half2*)(Ch + (size_t)gr * ldc + gc)       = __floats2half2_rn(w0, w1);
                    *(__half2*)(Ch + (size_t)(gr + 8) * ldc + gc) = __floats2half2_rn(w2, w3);
                } else {
                    float2 o0, o1;
                    o0.x = acc[mt][nt][0] * inv0;
                    o0.y = acc[mt][nt][1] * inv0;
                    o1.x = acc[mt][nt][2] * inv1;
                    o1.y = acc[mt][nt][3] * inv1;
                    *(float2*)(Cf + (size_t)gr * ldc + gc)       = o0;
                    *(float2*)(Cf + (size_t)(gr + 8) * ldc + gc) = o1;
                }
            }
            if (MODE == 1) {
                // quad-lane reduce: lanes differing in (lane&3) share the row
                rs0 += __shfl_xor_sync(0xffffffffu, rs0, 1);
                rs0 += __shfl_xor_sync(0xffffffffu, rs0, 2);
                rs1 += __shfl_xor_sync(0xffffffffu, rs1, 1);
                rs1 += __shfl_xor_sync(0xffffffffu, rs1, 2);
                if ((lane & 3) == 0) {
                    atomicAdd(&sred[gr - row0], rs0);
                    atomicAdd(&sred[gr + 8 - row0], rs1);
                }
            }
        }
        if (MODE == 1) {
            __syncthreads();
            if (tid < 128)
                atomicAdd(&g_l[(size_t)z * SEQ + row0 + tid], sred[tid]);
        }
    }
}

// ---------------------------------------------------------------------------
// Merged prep kernel: blocks [0, CONV_BLOCKS) convert x fp32->fp16;
// blocks [CONV_BLOCKS, CONV_BLOCKS+WT_BLOCKS) transpose+convert W.
// ---------------------------------------------------------------------------
__global__ __launch_bounds__(256)
void prep_kernel(const float* __restrict__ x,
                 const float* __restrict__ Wq, const float* __restrict__ Wk,
                 const float* __restrict__ Wv)
{
    __shared__ float t[32][33];
    const int bid = blockIdx.x;
    if (bid < CONV_BLOCKS) {
        const int idx = bid * 256 + threadIdx.x;   // one float4 each
        float4 v = *(const float4*)(x + (size_t)idx * 4);
        __half2* dst = (__half2*)(g_xh + (size_t)idx * 4);
        dst[0] = __floats2half2_rn(v.x, v.y);
        dst[1] = __floats2half2_rn(v.z, v.w);
    } else {
        const int b = bid - CONV_BLOCKS;           // 0..3071
        const int zz = b >> 10;                    // /1024
        const int rem = b & 1023;
        const float* W = (zz == 0 ? Wq : (zz == 1 ? Wk : Wv));
        const int x0 = (rem & 31) * 32;   // n
        const int y0 = (rem >> 5) * 32;   // k
        const int tx = threadIdx.x & 31, ty = threadIdx.x >> 5;
#pragma unroll
        for (int j = 0; j < 4; j++)
            t[ty + j * 8][tx] = W[(size_t)(y0 + ty + j * 8) * DIM + x0 + tx];
        __syncthreads();
        __half* out = g_wth + (size_t)zz * DIM * DIM;
#pragma unroll
        for (int j = 0; j < 4; j++)
            out[(size_t)(x0 + ty + j * 8) * DIM + y0 + tx] =
                __float2half_rn(t[tx][ty + j * 8]);
    }
}

// ---------------------------------------------------------------------------
extern "C" void kernel_launch(void* const* d_in, const int* in_sizes, int n_in,
                              void* d_out, int out_size)
{
    const float* x  = (const float*)d_in[0];
    const float* Wq = (const float*)d_in[1];
    const float* bq = (const float*)d_in[2];
    const float* Wk = (const float*)d_in[3];
    const float* bk = (const float*)d_in[4];
    const float* Wv = (const float*)d_in[5];
    const float* bv = (const float*)d_in[6];
    float* out = (float*)d_out;

    cudaFuncSetAttribute(gemm_nt<0>, cudaFuncAttributeMaxDynamicSharedMemorySize, SMEM_BYTES);
    cudaFuncSetAttribute(gemm_nt<1>, cudaFuncAttributeMaxDynamicSharedMemorySize, SMEM_BYTES);
    cudaFuncSetAttribute(gemm_nt<2>, cudaFuncAttributeMaxDynamicSharedMemorySize, SMEM_BYTES);

    // zero the row-sum accumulators (graph-capturable memset, no alloc)
    void* lptr = nullptr;
    cudaGetSymbolAddress(&lptr, g_l);
    cudaMemsetAsync(lptr, 0, MTOT * sizeof(float));

    // merged prep: x conversion + W transpose in one launch
    prep_kernel<<<CONV_BLOCKS + WT_BLOCKS, 256>>>(x, Wq, Wk, Wv);

    // QKV (z=2 writes v^T directly)
    {
        dim3 g(DIM / 128, MTOT / 128, 3);
        gemm_nt<0><<<g, NTHR_G, SMEM_BYTES>>>(nullptr, bq, bk, bv);
    }
    // scores -> unnormalized exp weights (fp16) + fused row sums
    {
        dim3 g(SEQ / 128, SEQ / 128, BATCH);
        gemm_nt<1><<<g, NTHR_G, SMEM_BYTES>>>(nullptr, nullptr, nullptr, nullptr);
    }
    // PV with 1/l scaling in epilogue (heavy rows launched first)
    {
        dim3 g(DIM / 128, SEQ / 128, BATCH);
        gemm_nt<2><<<g, NTHR_G, SMEM_BYTES>>>(out, nullptr, nullptr, nullptr);
    }
}

// round 17
// speedup vs baseline: 1.2189x; 1.0005x over previous
#include <cuda_runtime.h>
#include <cuda_fp16.h>
#include <math.h>
#include <stdint.h>

// ---------------------------------------------------------------------------
// Problem constants
// ---------------------------------------------------------------------------
#define BATCH 4
#define SEQ   4096
#define DIM   1024
#define MTOT  (BATCH * SEQ)     // 16384

#define NTHR_G 256              // 8 warps per GEMM CTA (2x4 grid of 64x32 tiles)
#define STAGES 3
#define BK     64               // halves per k-chunk (128 B per row)
#define TILE_B  16384           // 128 rows x 128 bytes
#define STAGE_B (2 * TILE_B)
#define SMEM_BYTES (STAGES * STAGE_B)   // 98304 (2 CTAs/SM)

// transpose staging: 128 x 136 halves (pad 8 -> conflict-free column walks)
#define TPAD 136

// merged prep kernel split points
#define CONV_BLOCKS (MTOT * DIM / (256 * 4))        // 16384
#define WT_BLOCKS   (3 * (DIM / 32) * (DIM / 32))   // 3072
#define ZL_BLOCKS   16                              // zero g_l (16384 floats)

// scores: triangular grid, 32x32 block-tiles lower triangle
#define TRI_BLOCKS  (32 * 33 / 2)                   // 528

// ---------------------------------------------------------------------------
// Scratch (__device__ globals: allocation-free rule)
// ---------------------------------------------------------------------------
__device__ __half g_xh[MTOT * DIM];                  // fp16 x
__device__ __half g_wth[3 * DIM * DIM];              // W^T fp16 (q,k,v)
__device__ __half g_qh[MTOT * DIM];
__device__ __half g_kh[MTOT * DIM];
__device__ __half g_vth[(size_t)BATCH * DIM * SEQ];  // v^T fp16 (written by QKV z=2)
__device__ __half g_sh[(size_t)BATCH * SEQ * SEQ];   // UNNORMALIZED exp weights fp16
__device__ float  g_l[MTOT];                         // per-row weight sums

// ---------------------------------------------------------------------------
// Helpers
// ---------------------------------------------------------------------------
__device__ __forceinline__ uint32_t smem_u32(const void* p) {
    return (uint32_t)__cvta_generic_to_shared(p);
}

__device__ __forceinline__ void cp16(uint32_t dst, const void* src) {
    asm volatile("cp.async.cg.shared.global [%0], [%1], 16;\n" :: "r"(dst), "l"(src));
}
#define CP_COMMIT() asm volatile("cp.async.commit_group;\n")
#define CP_WAIT1()  asm volatile("cp.async.wait_group 1;\n")
#define CP_WAIT0()  asm volatile("cp.async.wait_group 0;\n")

__device__ __forceinline__ void ldsm4(uint32_t* r, uint32_t addr) {
    asm volatile("ldmatrix.sync.aligned.m8n8.x4.shared.b16 {%0,%1,%2,%3}, [%4];"
                 : "=r"(r[0]), "=r"(r[1]), "=r"(r[2]), "=r"(r[3]) : "r"(addr));
}

__device__ __forceinline__ void mma16(float* d, const uint32_t* a, const uint32_t* b) {
    asm volatile(
        "mma.sync.aligned.m16n8k16.row.col.f32.f16.f16.f32 "
        "{%0,%1,%2,%3}, {%4,%5,%6,%7}, {%8,%9}, {%0,%1,%2,%3};\n"
        : "+f"(d[0]), "+f"(d[1]), "+f"(d[2]), "+f"(d[3])
        : "r"(a[0]), "r"(a[1]), "r"(a[2]), "r"(a[3]), "r"(b[0]), "r"(b[1]));
}

// exp2 with clamp: keeps fp16 finite even for pathological scores
__device__ __forceinline__ float wexp(float s, float c2) {
    return exp2f(fminf(s * c2, 15.0f));
}

// ---------------------------------------------------------------------------
// Tile fill: 128 rows x 64 halves (128B/row), swizzled chunk = c16 ^ (r&7).
// 256 threads, 4 chunks each.
// ---------------------------------------------------------------------------
__device__ __forceinline__ void fill_tile(uint32_t sdst, const __half* __restrict__ g,
                                          int ld, int k0) {
    const int tid = threadIdx.x;
#pragma unroll
    for (int i = 0; i < 4; i++) {
        int c = tid + i * 256;
        int r = c >> 3, c16 = c & 7;
        cp16(sdst + r * 128 + ((c16 ^ (r & 7)) << 4),
             g + (size_t)r * ld + k0 + c16 * 8);
    }
}

// ---------------------------------------------------------------------------
// Unified NT fp16 GEMM: C[128x128] = A(row-major,K-contig) . B^T(K-contig rows)
// 8 warps (2x4 grid), warp tile 64x32, m16n8k16, 3-stage cp.async pipeline,
// one barrier per K-iter. (R8 config: 2 CTAs/SM — do not reduce.)
// MODE 0: QKV    A=g_xh, B=g_wth[z]. z=0/1 -> g_qh/g_kh row-major (+bias).
//                z=2 -> v^T written DIRECTLY to g_vth via smem-staged
//                in-tile transpose (+bias before transpose).
// MODE 1: scores A=g_qh[z],B=g_kh[z], C=g_sh: w = exp2(s*c2) fp16, causal
//                mask, fused row-sum atomics. TRIANGULAR grid: blockIdx.x
//                in [0,528) decodes to lower-triangle (row,col) tile.
// MODE 2: PV     A=g_sh[z],B=g_vth[z],C=out fp32 scaled by 1/g_l[row];
//                blockIdx.y REVERSED (heavy rows first) for tail packing
// ---------------------------------------------------------------------------
template <int MODE>
__global__ __launch_bounds__(NTHR_G, 2)
void gemm_nt(float* __restrict__ Cout,
             const float* __restrict__ b0, const float* __restrict__ b1,
             const float* __restrict__ b2)
{
    int row0, col0;
    if (MODE == 1) {
        // triangular decode: blockIdx.x -> (rt, ct), ct <= rt
        const int bid = blockIdx.x;
        int rt = (int)((sqrtf(8.0f * (float)bid + 1.0f) - 1.0f) * 0.5f);
        while ((rt + 1) * (rt + 2) / 2 <= bid) rt++;
        while (rt * (rt + 1) / 2 > bid) rt--;
        const int ct = bid - rt * (rt + 1) / 2;
        row0 = rt * 128;
        col0 = ct * 128;
    } else if (MODE == 2) {
        row0 = (gridDim.y - 1 - blockIdx.y) * 128;   // heavy rows first
        col0 = blockIdx.x * 128;
    } else {
        row0 = blockIdx.y * 128;
        col0 = blockIdx.x * 128;
    }
    const int z = blockIdx.z;

    const __half *A, *B;
    const float* bias = nullptr;
    __half* Ch = nullptr;
    float* Cf = nullptr;
    int lda, ldb, ldc, nK;
    if (MODE == 0) {
        A = g_xh; lda = DIM;
        B = g_wth + (size_t)z * DIM * DIM; ldb = DIM;
        Ch = (z == 0 ? g_qh : (z == 1 ? g_kh : nullptr)); ldc = DIM;
        bias = (z == 0 ? b0 : (z == 1 ? b1 : b2));
        nK = DIM / BK;
    } else if (MODE == 1) {
        A = g_qh + (size_t)z * SEQ * DIM; lda = DIM;
        B = g_kh + (size_t)z * SEQ * DIM; ldb = DIM;
        Ch = g_sh + (size_t)z * SEQ * SEQ; ldc = SEQ;
        nK = DIM / BK;
    } else {
        A = g_sh + (size_t)z * SEQ * SEQ; lda = SEQ;
        B = g_vth + (size_t)z * DIM * SEQ; ldb = SEQ;
        Cf = Cout + (size_t)z * SEQ * DIM; ldc = DIM;
        nK = (row0 + 128) / BK;
    }
    const __half* Arow = A + (size_t)row0 * lda;
    const __half* Brow = B + (size_t)col0 * ldb;

    extern __shared__ char smem[];
    __shared__ float sred[128];   // MODE 1 row-sum reduction buffer
    const uint32_t sbase = smem_u32(smem);

    const int tid  = threadIdx.x;
    const int lane = tid & 31, warp = tid >> 5;
    const int wm = warp & 1, wn = warp >> 1;      // 2x4 warp grid: 64x32 tiles
    const int mat = lane >> 3, rl = lane & 7;     // ldmatrix address lanes

    float acc[4][4][4];
#pragma unroll
    for (int i = 0; i < 4; i++)
#pragma unroll
        for (int j = 0; j < 4; j++)
#pragma unroll
            for (int t = 0; t < 4; t++) acc[i][j][t] = 0.0f;

    if (MODE == 1) {
        if (tid < 128) sred[tid] = 0.0f;
    }

    // prologue: stages 0 and 1
    fill_tile(sbase, Arow, lda, 0);
    fill_tile(sbase + TILE_B, Brow, ldb, 0);
    CP_COMMIT();
    fill_tile(sbase + STAGE_B, Arow, lda, BK);
    fill_tile(sbase + STAGE_B + TILE_B, Brow, ldb, BK);
    CP_COMMIT();

    for (int it = 0; it < nK; ++it) {
        if (it + 1 < nK) { CP_WAIT1(); } else { CP_WAIT0(); }
        __syncthreads();
        // Barrier proves all warps finished reading stage (it-1), so the
        // prefetch into slot (it+2)%3 == (it-1)%3 is safe: one barrier/iter.
        if (it + 2 < nK) {
            const int slot = (it + 2) % STAGES;
            fill_tile(sbase + slot * STAGE_B, Arow, lda, (it + 2) * BK);
            fill_tile(sbase + slot * STAGE_B + TILE_B, Brow, ldb, (it + 2) * BK);
            CP_COMMIT();
        }

        const uint32_t sA = sbase + (it % STAGES) * STAGE_B;
        const uint32_t sB = sA + TILE_B;

#pragma unroll
        for (int kk = 0; kk < 4; kk++) {          // 4 x k16 per BK=64
            const int klo = kk * 2;               // 16B chunk index

            uint32_t a[4][4];
#pragma unroll
            for (int mt = 0; mt < 4; mt++) {
                int row = wm * 64 + mt * 16 + ((mat & 1) << 3) + rl;
                int c16 = klo + (mat >> 1);
                ldsm4(a[mt], sA + row * 128 + ((c16 ^ (row & 7)) << 4));
            }
            uint32_t b[4][2];
#pragma unroll
            for (int t = 0; t < 2; t++) {
                int nrow = wn * 32 + t * 16 + ((mat >> 1) << 3) + rl;
                int c16 = klo + (mat & 1);
                uint32_t r4[4];
                ldsm4(r4, sB + nrow * 128 + ((c16 ^ (nrow & 7)) << 4));
                b[2 * t][0] = r4[0]; b[2 * t][1] = r4[1];
                b[2 * t + 1][0] = r4[2]; b[2 * t + 1][1] = r4[3];
            }
#pragma unroll
            for (int mt = 0; mt < 4; mt++)
#pragma unroll
                for (int nt = 0; nt < 4; nt++)
                    mma16(acc[mt][nt], a[mt], b[nt]);
        }
    }

    // Epilogue
    const int gr0 = row0 + wm * 64 + (lane >> 2);
    const int gc0 = col0 + wn * 32 + (lane & 3) * 2;
    const float c2 = 0.03125f * 1.4426950408889634f;   // (1/sqrt(1024)) * log2(e)
    const bool diag = (MODE == 1) && (col0 == row0);

    if (MODE == 0 && z == 2) {
        // v path: add bias, stage tile [m][n] in smem, write transposed g_vth.
        __syncthreads();   // pipeline smem is dead; safe to reuse
        __half* st = (__half*)smem;   // [128][TPAD]
        const int lm0 = wm * 64 + (lane >> 2);
        const int ln0 = wn * 32 + (lane & 3) * 2;
#pragma unroll
        for (int mt = 0; mt < 4; mt++) {
            const int lm = lm0 + mt * 16;
#pragma unroll
            for (int nt = 0; nt < 4; nt++) {
                const int ln = ln0 + nt * 8;
                float2 bb = *(const float2*)(bias + col0 + ln);
                *(__half2*)(st + lm * TPAD + ln) =
                    __floats2half2_rn(acc[mt][nt][0] + bb.x, acc[mt][nt][1] + bb.y);
                *(__half2*)(st + (lm + 8) * TPAD + ln) =
                    __floats2half2_rn(acc[mt][nt][2] + bb.x, acc[mt][nt][3] + bb.y);
            }
        }
        __syncthreads();
        // write transposed: d-row = col0+n, s-cols = row0..row0+127.
        // 256 threads: 2 threads per n (each 64 halves = 128B, coalesced).
        const int n = tid >> 1;               // 0..127
        const int mhalf = (tid & 1) * 64;     // 0 or 64
        const int bz = row0 / SEQ;            // batch from global row
        const size_t srow = (size_t)(row0 - bz * SEQ);
        __half* orow = g_vth + (size_t)bz * DIM * SEQ + (size_t)(col0 + n) * SEQ
                       + srow + mhalf;
#pragma unroll
        for (int i = 0; i < 64; i += 8) {
            __half tmp[8];
#pragma unroll
            for (int u = 0; u < 8; u++) tmp[u] = st[(mhalf + i + u) * TPAD + n];
            *(float4*)(orow + i) = *(float4*)tmp;
        }
    } else {
#pragma unroll
        for (int mt = 0; mt < 4; mt++) {
            const int gr = gr0 + mt * 16;
            float inv0 = 1.0f, inv1 = 1.0f;
            if (MODE == 2) {
                inv0 = __frcp_rn(g_l[(size_t)z * SEQ + gr]);
                inv1 = __frcp_rn(g_l[(size_t)z * SEQ + gr + 8]);
            }
            float rs0 = 0.0f, rs1 = 0.0f;   // MODE 1: row sums for gr, gr+8
#pragma unroll
            for (int nt = 0; nt < 4; nt++) {
                const int gc = gc0 + nt * 8;
                if (MODE == 0) {
                    float2 bb = *(const float2*)(bias + gc);
                    __half2 h0 = __floats2half2_rn(acc[mt][nt][0] + bb.x,
                                                   acc[mt][nt][1] + bb.y);
                    __half2 h1 = __floats2half2_rn(acc[mt][nt][2] + bb.x,
                                                   acc[mt][nt][3] + bb.y);
                    *(__half2*)(Ch + (size_t)gr * ldc + gc)       = h0;
                    *(__half2*)(Ch + (size_t)(gr + 8) * ldc + gc) = h1;
                } else if (MODE == 1) {
                    float w0 = wexp(acc[mt][nt][0], c2);
                    float w1 = wexp(acc[mt][nt][1], c2);
                    float w2 = wexp(acc[mt][nt][2], c2);
                    float w3 = wexp(acc[mt][nt][3], c2);
                    if (diag) {
                        if (gc > gr)         w0 = 0.0f;
                        if (gc + 1 > gr)     w1 = 0.0f;
                        if (gc > gr + 8)     w2 = 0.0f;
                        if (gc + 1 > gr + 8) w3 = 0.0f;
                    }
                    rs0 += w0 + w1;
                    rs1 += w2 + w3;
                    *(__half2*)(Ch + (size_t)gr * ldc + gc)       = __floats2half2_rn(w0, w1);
                    *(__half2*)(Ch + (size_t)(gr + 8) * ldc + gc) = __floats2half2_rn(w2, w3);
                } else {
                    float2 o0, o1;
                    o0.x = acc[mt][nt][0] * inv0;
                    o0.y = acc[mt][nt][1] * inv0;
                    o1.x = acc[mt][nt][2] * inv1;
                    o1.y = acc[mt][nt][3] * inv1;
                    *(float2*)(Cf + (size_t)gr * ldc + gc)       = o0;
                    *(float2*)(Cf + (size_t)(gr + 8) * ldc + gc) = o1;
                }
            }
            if (MODE == 1) {
                // quad-lane reduce: lanes differing in (lane&3) share the row
                rs0 += __shfl_xor_sync(0xffffffffu, rs0, 1);
                rs0 += __shfl_xor_sync(0xffffffffu, rs0, 2);
                rs1 += __shfl_xor_sync(0xffffffffu, rs1, 1);
                rs1 += __shfl_xor_sync(0xffffffffu, rs1, 2);
                if ((lane & 3) == 0) {
                    atomicAdd(&sred[gr - row0], rs0);
                    atomicAdd(&sred[gr + 8 - row0], rs1);
                }
            }
        }
        if (MODE == 1) {
            __syncthreads();
            if (tid < 128)
                atomicAdd(&g_l[(size_t)z * SEQ + row0 + tid], sred[tid]);
        }
    }
}

// ---------------------------------------------------------------------------
// Merged prep kernel:
//   blocks [0, CONV_BLOCKS)                      convert x fp32->fp16
//   blocks [CONV_BLOCKS, CONV+WT)                transpose+convert W
//   blocks [CONV+WT, CONV+WT+ZL_BLOCKS)          zero g_l
// ---------------------------------------------------------------------------
__global__ __launch_bounds__(256)
void prep_kernel(const float* __restrict__ x,
                 const float* __restrict__ Wq, const float* __restrict__ Wk,
                 const float* __restrict__ Wv)
{
    __shared__ float t[32][33];
    const int bid = blockIdx.x;
    if (bid < CONV_BLOCKS) {
        const int idx = bid * 256 + threadIdx.x;   // one float4 each
        float4 v = *(const float4*)(x + (size_t)idx * 4);
        __half2* dst = (__half2*)(g_xh + (size_t)idx * 4);
        dst[0] = __floats2half2_rn(v.x, v.y);
        dst[1] = __floats2half2_rn(v.z, v.w);
    } else if (bid < CONV_BLOCKS + WT_BLOCKS) {
        const int b = bid - CONV_BLOCKS;           // 0..3071
        const int zz = b >> 10;                    // /1024
        const int rem = b & 1023;
        const float* W = (zz == 0 ? Wq : (zz == 1 ? Wk : Wv));
        const int x0 = (rem & 31) * 32;   // n
        const int y0 = (rem >> 5) * 32;   // k
        const int tx = threadIdx.x & 31, ty = threadIdx.x >> 5;
#pragma unroll
        for (int j = 0; j < 4; j++)
            t[ty + j * 8][tx] = W[(size_t)(y0 + ty + j * 8) * DIM + x0 + tx];
        __syncthreads();
        __half* out = g_wth + (size_t)zz * DIM * DIM;
#pragma unroll
        for (int j = 0; j < 4; j++)
            out[(size_t)(x0 + ty + j * 8) * DIM + y0 + tx] =
                __float2half_rn(t[tx][ty + j * 8]);
    } else {
        const int b = bid - CONV_BLOCKS - WT_BLOCKS;   // 0..15
        const int idx = (b * 256 + threadIdx.x) * 4;   // 4 floats each
        *(float4*)(g_l + idx) = make_float4(0.f, 0.f, 0.f, 0.f);
    }
}

// ---------------------------------------------------------------------------
extern "C" void kernel_launch(void* const* d_in, const int* in_sizes, int n_in,
                              void* d_out, int out_size)
{
    const float* x  = (const float*)d_in[0];
    const float* Wq = (const float*)d_in[1];
    const float* bq = (const float*)d_in[2];
    const float* Wk = (const float*)d_in[3];
    const float* bk = (const float*)d_in[4];
    const float* Wv = (const float*)d_in[5];
    const float* bv = (const float*)d_in[6];
    float* out = (float*)d_out;

    cudaFuncSetAttribute(gemm_nt<0>, cudaFuncAttributeMaxDynamicSharedMemorySize, SMEM_BYTES);
    cudaFuncSetAttribute(gemm_nt<1>, cudaFuncAttributeMaxDynamicSharedMemorySize, SMEM_BYTES);
    cudaFuncSetAttribute(gemm_nt<2>, cudaFuncAttributeMaxDynamicSharedMemorySize, SMEM_BYTES);

    // merged prep: x conversion + W transpose + g_l zeroing in one launch
    prep_kernel<<<CONV_BLOCKS + WT_BLOCKS + ZL_BLOCKS, 256>>>(x, Wq, Wk, Wv);

    // QKV (z=2 writes v^T directly)
    {
        dim3 g(DIM / 128, MTOT / 128, 3);
        gemm_nt<0><<<g, NTHR_G, SMEM_BYTES>>>(nullptr, bq, bk, bv);
    }
    // scores: triangular grid -> unnormalized exp weights + fused row sums
    {
        dim3 g(TRI_BLOCKS, 1, BATCH);
        gemm_nt<1><<<g, NTHR_G, SMEM_BYTES>>>(nullptr, nullptr, nullptr, nullptr);
    }
    // PV with 1/l scaling in epilogue (heavy rows launched first)
    {
        dim3 g(DIM / 128, SEQ / 128, BATCH);
        gemm_nt<2><<<g, NTHR_G, SMEM_BYTES>>>(out, nullptr, nullptr, nullptr);
    }
}